// round 13
// baseline (speedup 1.0000x reference)
#include <cuda_runtime.h>
#include <cuda_fp16.h>
#include <cstdint>

#define NB 4
#define C  128
#define Q  4096   // HS*WS = HR*WR
#define S  64
#define WS_ 64
#define HS_ 64

#define PT   128           // p rows per CTA
#define QC   128           // q cols per chunk (= 2 src-image rows)
#define NCH  (Q / QC)      // 32 chunks

// ---------------- device scratch ----------------
__device__ __half g_fr_h[(size_t)NB * Q * C];     // (n,p,c) fp16
__device__ __half g_fs_h[(size_t)NB * Q * C];     // (n,q,c) fp16
// One event per sample, sorted by trigger chunk t = yc1>>1.
// meta = s | r1<<6 | r0sel<<7 | x0<<9 | x1<<15
// w = (wa0, wa1, wb0, wb1) * cm * mv   (row yc0 weights, row yc1 weights)
__device__ uint32_t g_emeta[(size_t)NB * Q * S];
__device__ float4   g_ew[(size_t)NB * Q * S];
__device__ uint32_t g_eoff[(size_t)NB * Q * 33];

// ---------------- smem layout (bytes) ----------------
static constexpr int SA    = 0;                    // 32768  A tile (swizzled fp16)
static constexpr int SB    = 32768;                // 3 x 32768 B ring
static constexpr int SCE   = SB + 3 * 32768;       // 131072: even-row corr ring [2]
static constexpr int RBUF  = 128 * 72 * 2;         // 18432 per row buffer
static constexpr int SCO   = SCE + 2 * RBUF;       // 167936: odd-row corr ring [3]
static constexpr int SMEM_TOTAL = SCO + 3 * RBUF;  // 223232

// ---------------- helpers ----------------
__device__ __forceinline__ uint32_t smem_u32(const void* p) {
    uint32_t a;
    asm("{ .reg .u64 t; cvta.to.shared.u64 t, %1; cvt.u32.u64 %0, t; }"
        : "=r"(a) : "l"(p));
    return a;
}
// 256B-row smem swizzle for 16B chunks (conflict-free ldmatrix).
__device__ __forceinline__ uint32_t swz(int row, int c16) {
    return (uint32_t)row * 256u + (uint32_t)((c16 ^ (row & 7)) << 4);
}
__device__ __forceinline__ void ldsm4(uint32_t* r, uint32_t addr) {
    asm volatile("ldmatrix.sync.aligned.m8n8.x4.shared.b16 {%0,%1,%2,%3}, [%4];"
                 : "=r"(r[0]), "=r"(r[1]), "=r"(r[2]), "=r"(r[3]) : "r"(addr));
}
// fp16-accumulate MMA: D(f16x2 x2) = A*B + D, ~2x the f32-acc rate.
__device__ __forceinline__ void mma16816h(uint32_t* d, const uint32_t* a,
                                          uint32_t b0, uint32_t b1) {
    asm volatile("mma.sync.aligned.m16n8k16.row.col.f16.f16.f16.f16 "
                 "{%0,%1}, {%2,%3,%4,%5}, {%6,%7}, {%0,%1};"
                 : "+r"(d[0]), "+r"(d[1])
                 : "r"(a[0]), "r"(a[1]), "r"(a[2]), "r"(a[3]), "r"(b0), "r"(b1));
}
__device__ __forceinline__ void cp16(uint32_t dst, const void* src) {
    asm volatile("cp.async.cg.shared.global [%0], [%1], 16;" :: "r"(dst), "l"(src));
}
__device__ __forceinline__ void cp_commit() {
    asm volatile("cp.async.commit_group;" ::: "memory");
}
__device__ __forceinline__ void cp_wait1() {
    asm volatile("cp.async.wait_group 1;" ::: "memory");
}
__device__ __forceinline__ void cp_wait0() {
    asm volatile("cp.async.wait_group 0;" ::: "memory");
}

// ---------------------------------------------------------------------------
// Prelude:
//   blocks [0,2048)     fr -> fp16 transpose (n,p,c)
//   blocks [2048,4096)  fs -> fp16 transpose (n,q,c)
//   blocks [4096,6144)  event builder (warp per (n,p)) + corr_mask output
__global__ __launch_bounds__(256)
void prelude_kernel(const float* __restrict__ fr,
                    const float* __restrict__ fs,
                    const float* __restrict__ grids,
                    const float* __restrict__ mask,
                    float* __restrict__ out) {
    const int bid = blockIdx.x;
    const int tid = threadIdx.x;

    if (bid < 4096) {
        __shared__ float tile[32][33];
        const bool is_fs = bid >= 2048;
        const int  b  = bid & 2047;
        const int  n  = b >> 9;
        const int  r  = b & 511;
        const int  q0 = (r >> 2) * 32;
        const int  c0 = (r & 3) * 32;
        const int  tx = tid & 31;
        const int  ty = tid >> 5;

        const float* src = is_fs ? fs : fr;
        const float* sp  = src + ((size_t)n * C + c0) * Q + q0;
#pragma unroll
        for (int k = 0; k < 4; ++k)
            tile[ty + k * 8][tx] = sp[(size_t)(ty + k * 8) * Q + tx];
        __syncthreads();

        __half* dst = (is_fs ? g_fs_h : g_fr_h) + ((size_t)n * Q + q0) * C + c0;
#pragma unroll
        for (int k = 0; k < 4; ++k)
            dst[(size_t)(ty + k * 8) * C + tx] = __float2half(tile[tx][ty + k * 8]);
        return;
    }

    // ---- event builder: warp wid handles p = p0 + wid ----
    __shared__ float    s_g[S][2][8];
    __shared__ float    s_m[S][8];
    __shared__ uint32_t s_off[8][32];

    const int b   = bid - 4096;            // 0..2047
    const int n   = b >> 9;
    const int p0  = (b & 511) * 8;
    const int wid = tid >> 5;
    const int lane = tid & 31;
    const int p   = p0 + wid;

    for (int i = tid; i < S * 2 * 8; i += 256) {
        const int s = i >> 4, xy = (i >> 3) & 1, j = i & 7;
        s_g[s][xy][j] = grids[(((size_t)n * S + s) * 2 + xy) * Q + p0 + j];
    }
    for (int i = tid; i < S * 8; i += 256) {
        const int s = i >> 3, j = i & 7;
        s_m[s][j] = mask[((size_t)n * S + s) * Q + p0 + j];
    }
    s_off[wid][lane] = 0;
    __syncthreads();

    uint32_t ev_meta[2];
    float4   ev_w[2];
    int      ev_t[2];
    float*   cmask = out + (size_t)NB * S * Q + (size_t)n * S * Q + p;

#pragma unroll
    for (int k = 0; k < 2; ++k) {
        const int s = lane + k * 32;
        const float gx = s_g[s][0][wid];
        const float gy = s_g[s][1][wid];
        const float mv = s_m[s][wid];

        const float ix = gx - 0.5f, iy = gy - 0.5f;
        const float x0f = floorf(ix), y0f = floorf(iy);
        const float wx1 = ix - x0f, wy1 = iy - y0f;
        const int x0i = (int)x0f, y0i = (int)y0f;

        const bool bx0 = (x0i >= 0) && (x0i < WS_);
        const bool bx1 = (x0i + 1 >= 0) && (x0i + 1 < WS_);
        const bool by0 = (y0i >= 0) && (y0i < HS_);
        const bool by1 = (y0i + 1 >= 0) && (y0i + 1 < HS_);

        float wa0 = (1.f - wx1) * (1.f - wy1) * ((bx0 && by0) ? 1.f : 0.f);
        float wa1 = wx1 * (1.f - wy1) * ((bx1 && by0) ? 1.f : 0.f);
        float wb0 = (1.f - wx1) * wy1 * ((bx0 && by1) ? 1.f : 0.f);
        float wb1 = wx1 * wy1 * ((bx1 && by1) ? 1.f : 0.f);

        const float msum = wa0 + wa1 + wb0 + wb1;
        const float cm = (msum < 0.9999f) ? 0.0f : 1.0f;
        const float f  = cm * mv;
        cmask[(size_t)s * Q] = f;

        const int xc0 = min(max(x0i, 0), WS_ - 1);
        const int xc1 = min(max(x0i + 1, 0), WS_ - 1);
        const int yc0 = min(max(y0i, 0), HS_ - 1);
        const int yc1 = min(max(y0i + 1, 0), HS_ - 1);

        const int t  = yc1 >> 1;
        const int r1 = yc1 & 1;
        const int r0sel = ((yc0 >> 1) == t) ? (yc0 & 1) : 2;

        ev_meta[k] = (uint32_t)s | ((uint32_t)r1 << 6) | ((uint32_t)r0sel << 7)
                   | ((uint32_t)xc0 << 9) | ((uint32_t)xc1 << 15);
        ev_w[k] = make_float4(wa0 * f, wa1 * f, wb0 * f, wb1 * f);
        ev_t[k] = t;
        atomicAdd(&s_off[wid][t], 1);
    }
    __syncwarp();

    // exclusive scan of counts over 32 chunks
    const uint32_t v = s_off[wid][lane];
    uint32_t x = v;
#pragma unroll
    for (int o = 1; o < 32; o <<= 1) {
        const uint32_t y = __shfl_up_sync(0xFFFFFFFFu, x, o);
        if (lane >= o) x += y;
    }
    const uint32_t excl = x - v;
    const size_t eob = ((size_t)n * Q + p) * 33;
    g_eoff[eob + lane] = excl;
    if (lane == 31) g_eoff[eob + 32] = x;   // = 64
    __syncwarp();
    s_off[wid][lane] = excl;
    __syncwarp();

    const size_t evb = ((size_t)n * Q + p) * S;
#pragma unroll
    for (int k = 0; k < 2; ++k) {
        const uint32_t pos = atomicAdd(&s_off[wid][ev_t[k]], 1);
        g_emeta[evb + pos] = ev_meta[k];
        g_ew[evb + pos]    = ev_w[k];
    }
}

// ---------------------------------------------------------------------------
// Fused warp-specialized GEMM + sampling. grid (Q/PT, NB), block 512.
// Warps 0-7: MMA producer -> even-row ring [2] / odd-row ring [3].
//   fp16 accumulation in TWO independent chains (even kx / odd kx, K=64 each)
//   combined with one HADD2 -- bounds fp16 accumulation error while getting
//   the 2x f16-acc HMMA rate. D fragments are already packed __half2 in the
//   exact ring-store layout (zero-conversion epilogue).
// Warps 8-15: B prefetch (triple-buffered cp.async) + sample trigger c-1.
__global__ __launch_bounds__(512, 1)
void corr_fused_kernel(float* __restrict__ out) {
    extern __shared__ char smem[];
    const uint32_t sb = smem_u32(smem);

    const int tid  = threadIdx.x;
    const int wid  = tid >> 5;
    const int lane = tid & 31;
    const int pb   = blockIdx.x * PT;
    const int n    = blockIdx.y;

    // ---- prologue: A tile (all threads), B0+B1 prefetch (samplers) ----
    const __half* Abase = g_fr_h + ((size_t)n * Q + pb) * C;
#pragma unroll
    for (int i = 0; i < 4; ++i) {
        const int j = tid + i * 512;
        const int row = j >> 4, c16 = j & 15;
        const uint4 vv = *(const uint4*)(Abase + (size_t)row * C + c16 * 8);
        *(uint4*)(smem + SA + swz(row, c16)) = vv;
    }
    const __half* Bbase = g_fs_h + (size_t)n * Q * C;
    if (tid >= 256) {
        const int sampid = tid - 256;
#pragma unroll
        for (int k = 0; k < 2; ++k) {
            const __half* Bsrc = Bbase + (size_t)k * QC * C;
#pragma unroll
            for (int i = 0; i < 8; ++i) {
                const int j = sampid + i * 256;
                const int row = j >> 4, c16 = j & 15;
                cp16(sb + SB + k * 32768 + swz(row, c16),
                     Bsrc + (size_t)row * C + c16 * 8);
            }
            cp_commit();
        }
        cp_wait1();   // B0 complete; B1 in flight with a full chunk of slack
    }
    __syncthreads();

    // MMA warp constants (warps 0-7): 4 m-groups x 2 n-groups.
    // nwarp=0 -> even source row (2c); nwarp=64 -> odd source row (2c+1).
    const int mwarp = (wid >> 1) * 32;
    const int nwarp = (wid & 1) * 64;
    const int arow0 = mwarp + (lane & 15);
    const int ac16k = (lane >> 4);
    const int brow0 = nwarp + ((lane >> 4) << 3) + (lane & 7);
    const int bc16k = ((lane >> 3) & 1);

    for (int c = 0; c <= NCH; ++c) {
        if (tid >= 256) {
            const int sampid = tid - 256;
            // prefetch B(c+2) into ring slot (c+2)%3
            if (c + 2 < NCH) {
                const uint32_t bdst = sb + SB + ((c + 2) % 3) * 32768;
                const __half* Bsrc = Bbase + (size_t)(c + 2) * QC * C;
#pragma unroll
                for (int i = 0; i < 8; ++i) {
                    const int j = sampid + i * 256;
                    const int row = j >> 4, c16 = j & 15;
                    cp16(bdst + swz(row, c16), Bsrc + (size_t)row * C + c16 * 8);
                }
                cp_commit();
            }
            // sample trigger t = c-1 from corr rings
            if (c >= 1) {
                const int t = c - 1;
                const __half* ce = (const __half*)(smem + SCE + (size_t)(t & 1) * RBUF);
                const __half* co = (const __half*)(smem + SCO + (size_t)(t % 3) * RBUF);
                const __half* cp = (const __half*)(smem + SCO + (size_t)((t + 2) % 3) * RBUF);

                const int prow = sampid >> 1;
                const int slot = sampid & 1;
                const size_t pbase = (size_t)n * Q + pb + prow;
                const uint32_t e0 = __ldg(&g_eoff[pbase * 33 + t]);
                const uint32_t e1 = __ldg(&g_eoff[pbase * 33 + t + 1]);
                const uint32_t* mp = g_emeta + pbase * S;
                const float4*   wp = g_ew + pbase * S;
                const size_t roff = (size_t)prow * 72;
                float* outb = out + (size_t)n * S * Q + pb + prow;

                for (uint32_t j = e0 + slot; j < e1; j += 2) {
                    const uint32_t m = __ldg(&mp[j]);
                    const float4  w = __ldg(&wp[j]);
                    const int s   = m & 63;
                    const int r1  = (m >> 6) & 1;
                    const int r0s = (m >> 7) & 3;
                    const int x0  = (m >> 9) & 63;
                    const int x1  = (m >> 15) & 63;
                    const __half* rb = (r1 ? co : ce) + roff;
                    const __half* ra = ((r0s == 2) ? cp : (r0s ? co : ce)) + roff;
                    const float vv = w.x * __half2float(ra[x0])
                                   + w.y * __half2float(ra[x1])
                                   + w.z * __half2float(rb[x0])
                                   + w.w * __half2float(rb[x1]);
                    outb[(size_t)s * Q] = vv;
                }
            }
            // ensure B(c+1) landed before the barrier releases chunk c+1
            if (c + 2 < NCH) cp_wait1();
            else             cp_wait0();
        } else if (c < NCH) {
            // ---- MMA: corr chunk c (rows 2c, 2c+1), fp16 dual-chain acc ----
            const uint32_t bbuf = sb + SB + (c % 3) * 32768;
            uint32_t accE[2][8][2], accO[2][8][2];
#pragma unroll
            for (int mi = 0; mi < 2; ++mi)
#pragma unroll
                for (int nt = 0; nt < 8; ++nt) {
                    accE[mi][nt][0] = 0u; accE[mi][nt][1] = 0u;
                    accO[mi][nt][0] = 0u; accO[mi][nt][1] = 0u;
                }

#pragma unroll
            for (int kk = 0; kk < 8; ++kk) {
                uint32_t a[2][4];
#pragma unroll
                for (int mi = 0; mi < 2; ++mi)
                    ldsm4(a[mi], sb + SA + swz(arow0 + mi * 16, 2 * kk + ac16k));
                uint32_t b4[4][4];
#pragma unroll
                for (int nbq = 0; nbq < 4; ++nbq)
                    ldsm4(b4[nbq], bbuf + swz(brow0 + nbq * 16, 2 * kk + bc16k));
#pragma unroll
                for (int mi = 0; mi < 2; ++mi)
#pragma unroll
                    for (int nt = 0; nt < 8; ++nt)
                        mma16816h((kk & 1) ? accO[mi][nt] : accE[mi][nt], a[mi],
                                  b4[nt >> 1][(nt & 1) * 2], b4[nt >> 1][(nt & 1) * 2 + 1]);
            }

            // store: even-row warps -> even ring [c&1], odd-row warps -> odd ring [c%3]
            __half* cbase = (wid & 1)
                ? (__half*)(smem + SCO + (size_t)(c % 3) * RBUF)
                : (__half*)(smem + SCE + (size_t)(c & 1) * RBUF);
            const int crow = lane >> 2;
            const int cc2  = (lane & 3) * 2;
#pragma unroll
            for (int mi = 0; mi < 2; ++mi)
#pragma unroll
                for (int nt = 0; nt < 8; ++nt) {
                    const int r0 = mwarp + mi * 16 + crow;
                    const int xx = nt * 8 + cc2;
                    const __half2 lo = __hadd2(*(__half2*)&accE[mi][nt][0],
                                               *(__half2*)&accO[mi][nt][0]);
                    const __half2 hi = __hadd2(*(__half2*)&accE[mi][nt][1],
                                               *(__half2*)&accO[mi][nt][1]);
                    *(__half2*)(cbase + (size_t)r0 * 72 + xx) = lo;
                    *(__half2*)(cbase + (size_t)(r0 + 8) * 72 + xx) = hi;
                }
        }
        __syncthreads();
    }
}

// ---------------------------------------------------------------------------
extern "C" void kernel_launch(void* const* d_in, const int* in_sizes, int n_in,
                              void* d_out, int out_size) {
    const float* fr    = (const float*)d_in[0];
    const float* fs    = (const float*)d_in[1];
    const float* grids = (const float*)d_in[2];
    const float* mask  = (const float*)d_in[3];
    float* out = (float*)d_out;

    cudaFuncSetAttribute(corr_fused_kernel,
                         cudaFuncAttributeMaxDynamicSharedMemorySize, SMEM_TOTAL);

    prelude_kernel<<<6144, 256>>>(fr, fs, grids, mask, out);
    corr_fused_kernel<<<dim3(Q / PT, NB), 512, SMEM_TOTAL>>>(out);
}

// round 14
// speedup vs baseline: 1.1055x; 1.1055x over previous
#include <cuda_runtime.h>
#include <cuda_fp16.h>
#include <cstdint>

#define NB 4
#define C  128
#define Q  4096   // HS*WS = HR*WR
#define S  64
#define WS_ 64
#define HS_ 64

#define PT   128           // p rows per CTA
#define QC   128           // q cols per chunk (= 2 src-image rows)
#define NCH  (Q / QC)      // 32 chunks

// ---------------- device scratch ----------------
__device__ __half g_fr_h[(size_t)NB * Q * C];     // (n,p,c) fp16
__device__ __half g_fs_h[(size_t)NB * Q * C];     // (n,q,c) fp16
// One event per sample, sorted by trigger chunk t = yc1>>1.
// meta = s | r1<<6 | r0sel<<7 | x0<<9 | x1<<15
// w = (wa0, wa1, wb0, wb1) * cm * mv   (row yc0 weights, row yc1 weights)
__device__ uint32_t g_emeta[(size_t)NB * Q * S];
__device__ float4   g_ew[(size_t)NB * Q * S];
__device__ uint32_t g_eoff[(size_t)NB * Q * 33];

// ---------------- smem layout (bytes) ----------------
static constexpr int SA    = 0;                    // 32768  A tile (swizzled fp16)
static constexpr int SB    = 32768;                // 3 x 32768 B ring
static constexpr int SCE   = SB + 3 * 32768;       // 131072: even-row corr ring [2]
static constexpr int RBUF  = 128 * 72 * 2;         // 18432 per row buffer
static constexpr int SCO   = SCE + 2 * RBUF;       // 167936: odd-row corr ring [3]
static constexpr int SMB   = SCO + 3 * RBUF;       // 223232: mbarriers
// SMB + 0:  full[0]   (producer->consumer, chunk even)
// SMB + 8:  full[1]
// SMB + 16: empty[0]  (consumer->producer)
// SMB + 24: empty[1]
static constexpr int SMEM_TOTAL = SMB + 32;        // 223264

// ---------------- helpers ----------------
__device__ __forceinline__ uint32_t smem_u32(const void* p) {
    uint32_t a;
    asm("{ .reg .u64 t; cvta.to.shared.u64 t, %1; cvt.u32.u64 %0, t; }"
        : "=r"(a) : "l"(p));
    return a;
}
// 256B-row smem swizzle for 16B chunks (conflict-free ldmatrix).
__device__ __forceinline__ uint32_t swz(int row, int c16) {
    return (uint32_t)row * 256u + (uint32_t)((c16 ^ (row & 7)) << 4);
}
__device__ __forceinline__ void ldsm4(uint32_t* r, uint32_t addr) {
    asm volatile("ldmatrix.sync.aligned.m8n8.x4.shared.b16 {%0,%1,%2,%3}, [%4];"
                 : "=r"(r[0]), "=r"(r[1]), "=r"(r[2]), "=r"(r[3]) : "r"(addr));
}
__device__ __forceinline__ void mma16816(float* d, const uint32_t* a,
                                         uint32_t b0, uint32_t b1) {
    asm volatile("mma.sync.aligned.m16n8k16.row.col.f32.f16.f16.f32 "
                 "{%0,%1,%2,%3}, {%4,%5,%6,%7}, {%8,%9}, {%0,%1,%2,%3};"
                 : "+f"(d[0]), "+f"(d[1]), "+f"(d[2]), "+f"(d[3])
                 : "r"(a[0]), "r"(a[1]), "r"(a[2]), "r"(a[3]), "r"(b0), "r"(b1));
}
__device__ __forceinline__ void cp16(uint32_t dst, const void* src) {
    asm volatile("cp.async.cg.shared.global [%0], [%1], 16;" :: "r"(dst), "l"(src));
}
__device__ __forceinline__ void cp_commit() {
    asm volatile("cp.async.commit_group;" ::: "memory");
}
__device__ __forceinline__ void cp_wait2() {
    asm volatile("cp.async.wait_group 2;" ::: "memory");
}
__device__ __forceinline__ void cp_wait1() {
    asm volatile("cp.async.wait_group 1;" ::: "memory");
}
__device__ __forceinline__ void cp_wait0() {
    asm volatile("cp.async.wait_group 0;" ::: "memory");
}

#define MBARRIER_INIT(mb, cnt) \
    asm volatile("mbarrier.init.shared.b64 [%0], %1;" \
                 :: "r"((uint32_t)(mb)), "r"((uint32_t)(cnt)) : "memory")
#define MBARRIER_ARRIVE(mb) \
    asm volatile("mbarrier.arrive.shared.b64 _, [%0];" \
                 :: "r"((uint32_t)(mb)) : "memory")
#define MBARRIER_WAIT_PARITY(mb, par) do {                                   \
    uint32_t _mb = (uint32_t)(mb), _pa = (uint32_t)(par), _dn;               \
    asm volatile("{\n\t.reg .pred p;\n\t"                                    \
        "mbarrier.try_wait.parity.acquire.cta.shared::cta.b64 p, [%1], %2;\n\t" \
        "selp.b32 %0,1,0,p;\n\t}" : "=r"(_dn) : "r"(_mb), "r"(_pa) : "memory"); \
    if (!_dn) {                                                              \
        asm volatile("{\n\t.reg .pred P1;\n\tWL_%=: \n\t"                    \
            "mbarrier.try_wait.parity.acquire.cta.shared::cta.b64 P1, [%0], %1, 0x989680;\n\t" \
            "@P1 bra.uni WD_%=;\n\tbra.uni WL_%=;\n\tWD_%=: \n\t}"           \
            :: "r"(_mb), "r"(_pa) : "memory");                               \
    }                                                                        \
} while (0)
#define BAR_SYNC(id, cnt) \
    asm volatile("bar.sync %0, %1;" :: "r"(id), "r"(cnt) : "memory")

// ---------------------------------------------------------------------------
// Prelude:
//   blocks [0,2048)     fr -> fp16 transpose (n,p,c)
//   blocks [2048,4096)  fs -> fp16 transpose (n,q,c)
//   blocks [4096,6144)  event builder (warp per (n,p)) + corr_mask output
__global__ __launch_bounds__(256)
void prelude_kernel(const float* __restrict__ fr,
                    const float* __restrict__ fs,
                    const float* __restrict__ grids,
                    const float* __restrict__ mask,
                    float* __restrict__ out) {
    const int bid = blockIdx.x;
    const int tid = threadIdx.x;

    if (bid < 4096) {
        __shared__ float tile[32][33];
        const bool is_fs = bid >= 2048;
        const int  b  = bid & 2047;
        const int  n  = b >> 9;
        const int  r  = b & 511;
        const int  q0 = (r >> 2) * 32;
        const int  c0 = (r & 3) * 32;
        const int  tx = tid & 31;
        const int  ty = tid >> 5;

        const float* src = is_fs ? fs : fr;
        const float* sp  = src + ((size_t)n * C + c0) * Q + q0;
#pragma unroll
        for (int k = 0; k < 4; ++k)
            tile[ty + k * 8][tx] = sp[(size_t)(ty + k * 8) * Q + tx];
        __syncthreads();

        __half* dst = (is_fs ? g_fs_h : g_fr_h) + ((size_t)n * Q + q0) * C + c0;
#pragma unroll
        for (int k = 0; k < 4; ++k)
            dst[(size_t)(ty + k * 8) * C + tx] = __float2half(tile[tx][ty + k * 8]);
        return;
    }

    // ---- event builder: warp wid handles p = p0 + wid ----
    __shared__ float    s_g[S][2][8];
    __shared__ float    s_m[S][8];
    __shared__ uint32_t s_off[8][32];

    const int b   = bid - 4096;            // 0..2047
    const int n   = b >> 9;
    const int p0  = (b & 511) * 8;
    const int wid = tid >> 5;
    const int lane = tid & 31;
    const int p   = p0 + wid;

    for (int i = tid; i < S * 2 * 8; i += 256) {
        const int s = i >> 4, xy = (i >> 3) & 1, j = i & 7;
        s_g[s][xy][j] = grids[(((size_t)n * S + s) * 2 + xy) * Q + p0 + j];
    }
    for (int i = tid; i < S * 8; i += 256) {
        const int s = i >> 3, j = i & 7;
        s_m[s][j] = mask[((size_t)n * S + s) * Q + p0 + j];
    }
    s_off[wid][lane] = 0;
    __syncthreads();

    uint32_t ev_meta[2];
    float4   ev_w[2];
    int      ev_t[2];
    float*   cmask = out + (size_t)NB * S * Q + (size_t)n * S * Q + p;

#pragma unroll
    for (int k = 0; k < 2; ++k) {
        const int s = lane + k * 32;
        const float gx = s_g[s][0][wid];
        const float gy = s_g[s][1][wid];
        const float mv = s_m[s][wid];

        const float ix = gx - 0.5f, iy = gy - 0.5f;
        const float x0f = floorf(ix), y0f = floorf(iy);
        const float wx1 = ix - x0f, wy1 = iy - y0f;
        const int x0i = (int)x0f, y0i = (int)y0f;

        const bool bx0 = (x0i >= 0) && (x0i < WS_);
        const bool bx1 = (x0i + 1 >= 0) && (x0i + 1 < WS_);
        const bool by0 = (y0i >= 0) && (y0i < HS_);
        const bool by1 = (y0i + 1 >= 0) && (y0i + 1 < HS_);

        float wa0 = (1.f - wx1) * (1.f - wy1) * ((bx0 && by0) ? 1.f : 0.f);
        float wa1 = wx1 * (1.f - wy1) * ((bx1 && by0) ? 1.f : 0.f);
        float wb0 = (1.f - wx1) * wy1 * ((bx0 && by1) ? 1.f : 0.f);
        float wb1 = wx1 * wy1 * ((bx1 && by1) ? 1.f : 0.f);

        const float msum = wa0 + wa1 + wb0 + wb1;
        const float cm = (msum < 0.9999f) ? 0.0f : 1.0f;
        const float f  = cm * mv;
        cmask[(size_t)s * Q] = f;

        const int xc0 = min(max(x0i, 0), WS_ - 1);
        const int xc1 = min(max(x0i + 1, 0), WS_ - 1);
        const int yc0 = min(max(y0i, 0), HS_ - 1);
        const int yc1 = min(max(y0i + 1, 0), HS_ - 1);

        const int t  = yc1 >> 1;
        const int r1 = yc1 & 1;
        const int r0sel = ((yc0 >> 1) == t) ? (yc0 & 1) : 2;

        ev_meta[k] = (uint32_t)s | ((uint32_t)r1 << 6) | ((uint32_t)r0sel << 7)
                   | ((uint32_t)xc0 << 9) | ((uint32_t)xc1 << 15);
        ev_w[k] = make_float4(wa0 * f, wa1 * f, wb0 * f, wb1 * f);
        ev_t[k] = t;
        atomicAdd(&s_off[wid][t], 1);
    }
    __syncwarp();

    // exclusive scan of counts over 32 chunks
    const uint32_t v = s_off[wid][lane];
    uint32_t x = v;
#pragma unroll
    for (int o = 1; o < 32; o <<= 1) {
        const uint32_t y = __shfl_up_sync(0xFFFFFFFFu, x, o);
        if (lane >= o) x += y;
    }
    const uint32_t excl = x - v;
    const size_t eob = ((size_t)n * Q + p) * 33;
    g_eoff[eob + lane] = excl;
    if (lane == 31) g_eoff[eob + 32] = x;   // = 64
    __syncwarp();
    s_off[wid][lane] = excl;
    __syncwarp();

    const size_t evb = ((size_t)n * Q + p) * S;
#pragma unroll
    for (int k = 0; k < 2; ++k) {
        const uint32_t pos = atomicAdd(&s_off[wid][ev_t[k]], 1);
        g_emeta[evb + pos] = ev_meta[k];
        g_ew[evb + pos]    = ev_w[k];
    }
}

// ---------------------------------------------------------------------------
// Fused warp-specialized GEMM + sampling, mbarrier-pipelined. block 512.
// Producers (warps 0-7): cp.async B (own consumption), MMA chunk c, then
//   wait empty[c&1] (sampler(c-2) done) ONLY at the ring store, arrive full.
// Consumers (warps 8-15): wait full[t&1], sample trigger t, arrive empty.
__global__ __launch_bounds__(512, 1)
void corr_fused_kernel(float* __restrict__ out) {
    extern __shared__ char smem[];
    const uint32_t sb = smem_u32(smem);

    const int tid  = threadIdx.x;
    const int wid  = tid >> 5;
    const int lane = tid & 31;
    const int pb   = blockIdx.x * PT;
    const int n    = blockIdx.y;

    if (tid == 0) {
        MBARRIER_INIT(sb + SMB + 0, 256);   // full[0]
        MBARRIER_INIT(sb + SMB + 8, 256);   // full[1]
        MBARRIER_INIT(sb + SMB + 16, 256);  // empty[0]
        MBARRIER_INIT(sb + SMB + 24, 256);  // empty[1]
    }

    // ---- prologue: A tile (all threads), B0+B1 (producers) ----
    const __half* Abase = g_fr_h + ((size_t)n * Q + pb) * C;
#pragma unroll
    for (int i = 0; i < 4; ++i) {
        const int j = tid + i * 512;
        const int row = j >> 4, c16 = j & 15;
        const uint4 vv = *(const uint4*)(Abase + (size_t)row * C + c16 * 8);
        *(uint4*)(smem + SA + swz(row, c16)) = vv;
    }
    const __half* Bbase = g_fs_h + (size_t)n * Q * C;
    if (tid < 256) {
#pragma unroll
        for (int k = 0; k < 2; ++k) {
            const __half* Bsrc = Bbase + (size_t)k * QC * C;
#pragma unroll
            for (int i = 0; i < 8; ++i) {
                const int j = tid + i * 256;
                const int row = j >> 4, c16 = j & 15;
                cp16(sb + SB + k * 32768 + swz(row, c16),
                     Bsrc + (size_t)row * C + c16 * 8);
            }
            cp_commit();
        }
    }
    __syncthreads();

    if (tid < 256) {
        // ================= producers =================
        const int mwarp = (wid >> 1) * 32;
        const int nwarp = (wid & 1) * 64;
        const int arow0 = mwarp + (lane & 15);
        const int ac16k = (lane >> 4);
        const int brow0 = nwarp + ((lane >> 4) << 3) + (lane & 7);
        const int bc16k = ((lane >> 3) & 1);

        int pphase = 1;   // first two empty-waits pass immediately
        for (int c = 0; c < NCH; ++c) {
            // issue B(c+2); ensure B(c) landed (own groups), then all producers
            if (c + 2 < NCH) {
                const uint32_t bdst = sb + SB + ((c + 2) % 3) * 32768;
                const __half* Bsrc = Bbase + (size_t)(c + 2) * QC * C;
#pragma unroll
                for (int i = 0; i < 8; ++i) {
                    const int j = tid + i * 256;
                    const int row = j >> 4, c16 = j & 15;
                    cp16(bdst + swz(row, c16), Bsrc + (size_t)row * C + c16 * 8);
                }
                cp_commit();
                cp_wait2();
            } else if (c + 1 < NCH) {
                cp_wait1();
            } else {
                cp_wait0();
            }
            BAR_SYNC(1, 256);   // B(c) visible across producer warps

            // ---- MMA chunk c into registers ----
            const uint32_t bbuf = sb + SB + (c % 3) * 32768;
            float acc[2][8][4];
#pragma unroll
            for (int mi = 0; mi < 2; ++mi)
#pragma unroll
                for (int nt = 0; nt < 8; ++nt)
#pragma unroll
                    for (int k = 0; k < 4; ++k) acc[mi][nt][k] = 0.0f;

#pragma unroll
            for (int kk = 0; kk < 8; ++kk) {
                uint32_t a[2][4];
#pragma unroll
                for (int mi = 0; mi < 2; ++mi)
                    ldsm4(a[mi], sb + SA + swz(arow0 + mi * 16, 2 * kk + ac16k));
                uint32_t b4[4][4];
#pragma unroll
                for (int nbq = 0; nbq < 4; ++nbq)
                    ldsm4(b4[nbq], bbuf + swz(brow0 + nbq * 16, 2 * kk + bc16k));
#pragma unroll
                for (int mi = 0; mi < 2; ++mi)
#pragma unroll
                    for (int nt = 0; nt < 8; ++nt)
                        mma16816(acc[mi][nt], a[mi],
                                 b4[nt >> 1][(nt & 1) * 2], b4[nt >> 1][(nt & 1) * 2 + 1]);
            }

            // ---- ring store: needs sampler(c-2) done with these slots ----
            MBARRIER_WAIT_PARITY(sb + SMB + 16 + (c & 1) * 8, pphase);
            __half* cbase = (wid & 1)
                ? (__half*)(smem + SCO + (size_t)(c % 3) * RBUF)
                : (__half*)(smem + SCE + (size_t)(c & 1) * RBUF);
            const int crow = lane >> 2;
            const int cc2  = (lane & 3) * 2;
#pragma unroll
            for (int mi = 0; mi < 2; ++mi)
#pragma unroll
                for (int nt = 0; nt < 8; ++nt) {
                    const int r0 = mwarp + mi * 16 + crow;
                    const int xx = nt * 8 + cc2;
                    *(__half2*)(cbase + (size_t)r0 * 72 + xx) =
                        __floats2half2_rn(acc[mi][nt][0], acc[mi][nt][1]);
                    *(__half2*)(cbase + (size_t)(r0 + 8) * 72 + xx) =
                        __floats2half2_rn(acc[mi][nt][2], acc[mi][nt][3]);
                }
            MBARRIER_ARRIVE(sb + SMB + (c & 1) * 8);   // full[c&1]
            if (c & 1) pphase ^= 1;
        }
    } else {
        // ================= consumers (samplers) =================
        const int sampid = tid - 256;
        const int prow = sampid >> 1;
        const int slot = sampid & 1;
        const size_t pbase = (size_t)n * Q + pb + prow;
        const uint32_t* eoffp = g_eoff + pbase * 33;
        const uint32_t* mp = g_emeta + pbase * S;
        const float4*   wp = g_ew + pbase * S;
        const size_t roff = (size_t)prow * 72;
        float* outb = out + (size_t)n * S * Q + pb + prow;

        int cphase = 0;
        for (int t = 0; t < NCH; ++t) {
            // static event data: load before the wait (latency overlapped)
            const uint32_t e0 = __ldg(&eoffp[t]);
            const uint32_t e1 = __ldg(&eoffp[t + 1]);
            uint32_t m0 = 0, m1 = 0;
            float4 w0, w1;
            bool h0 = false, h1 = false;
            const uint32_t j0 = e0 + slot;
            if (j0 < e1)     { m0 = __ldg(&mp[j0]);     w0 = __ldg(&wp[j0]);     h0 = true; }
            if (j0 + 2 < e1) { m1 = __ldg(&mp[j0 + 2]); w1 = __ldg(&wp[j0 + 2]); h1 = true; }

            MBARRIER_WAIT_PARITY(sb + SMB + (t & 1) * 8, cphase);   // full[t&1]

            const __half* ce  = (const __half*)(smem + SCE + (size_t)(t & 1) * RBUF) + roff;
            const __half* co  = (const __half*)(smem + SCO + (size_t)(t % 3) * RBUF) + roff;
            const __half* cpv = (const __half*)(smem + SCO + (size_t)((t + 2) % 3) * RBUF) + roff;

            if (h0) {
                const int s   = m0 & 63;
                const int r1  = (m0 >> 6) & 1;
                const int r0s = (m0 >> 7) & 3;
                const int x0  = (m0 >> 9) & 63;
                const int x1  = (m0 >> 15) & 63;
                const __half* rb = r1 ? co : ce;
                const __half* ra = (r0s == 2) ? cpv : (r0s ? co : ce);
                outb[(size_t)s * Q] = w0.x * __half2float(ra[x0])
                                    + w0.y * __half2float(ra[x1])
                                    + w0.z * __half2float(rb[x0])
                                    + w0.w * __half2float(rb[x1]);
            }
            if (h1) {
                const int s   = m1 & 63;
                const int r1  = (m1 >> 6) & 1;
                const int r0s = (m1 >> 7) & 3;
                const int x0  = (m1 >> 9) & 63;
                const int x1  = (m1 >> 15) & 63;
                const __half* rb = r1 ? co : ce;
                const __half* ra = (r0s == 2) ? cpv : (r0s ? co : ce);
                outb[(size_t)s * Q] = w1.x * __half2float(ra[x0])
                                    + w1.y * __half2float(ra[x1])
                                    + w1.z * __half2float(rb[x0])
                                    + w1.w * __half2float(rb[x1]);
            }
            // rare slow path: >2 events for this (prow, slot)
            for (uint32_t j = j0 + 4; j < e1; j += 2) {
                const uint32_t m = __ldg(&mp[j]);
                const float4  w = __ldg(&wp[j]);
                const int s   = m & 63;
                const int r1  = (m >> 6) & 1;
                const int r0s = (m >> 7) & 3;
                const int x0  = (m >> 9) & 63;
                const int x1  = (m >> 15) & 63;
                const __half* rb = r1 ? co : ce;
                const __half* ra = (r0s == 2) ? cpv : (r0s ? co : ce);
                outb[(size_t)s * Q] = w.x * __half2float(ra[x0])
                                    + w.y * __half2float(ra[x1])
                                    + w.z * __half2float(rb[x0])
                                    + w.w * __half2float(rb[x1]);
            }

            MBARRIER_ARRIVE(sb + SMB + 16 + (t & 1) * 8);   // empty[t&1]
            if (t & 1) cphase ^= 1;
        }
    }
}

// ---------------------------------------------------------------------------
extern "C" void kernel_launch(void* const* d_in, const int* in_sizes, int n_in,
                              void* d_out, int out_size) {
    const float* fr    = (const float*)d_in[0];
    const float* fs    = (const float*)d_in[1];
    const float* grids = (const float*)d_in[2];
    const float* mask  = (const float*)d_in[3];
    float* out = (float*)d_out;

    cudaFuncSetAttribute(corr_fused_kernel,
                         cudaFuncAttributeMaxDynamicSharedMemorySize, SMEM_TOTAL);

    prelude_kernel<<<6144, 256>>>(fr, fs, grids, mask, out);
    corr_fused_kernel<<<dim3(Q / PT, NB), 512, SMEM_TOTAL>>>(out);
}